// round 7
// baseline (speedup 1.0000x reference)
#include <cuda_runtime.h>
#include <cstdint>

// Problem dims
#define B_ 8
#define L_ 1024
#define D_ 512
#define H_ 8
#define DK_ 64
#define BL_ (B_ * L_)               // 8192
#define ATT_OFF ((size_t)BL_ * D_)  // start of attn in d_out

// GEMM tile config
#define BM 128
#define BN 64
#define BK 32
#define NTHR 256

#define ASZ (BM * 36)       // A stage floats
#define BSZ (BK * 72)       // B stage floats
#define SMEM_GEMM ((2 * ASZ + 2 * BSZ + 128) * 4)        // 55808 B
#define SMEM_SC   ((128 * 68 + 64 * 68 + 256) * 4)       // pass-1

// k_attn2 smem: Qs[128][68] Ps[128][68] Ks[64][68] Vs[64][72] rinv[128]
#define AT_QS 0
#define AT_PS (128 * 68)
#define AT_KS (AT_PS + 128 * 68)
#define AT_VS (AT_KS + 64 * 68)
#define AT_RI (AT_VS + 64 * 72)
#define AT_SMEM ((AT_RI + 128) * 4)     // 105,984 B

// Scratch (static device globals — no allocation)
__device__ float g_Q[BL_ * D_];
__device__ float g_K[BL_ * D_];
__device__ float g_V[BL_ * D_];
__device__ float g_O[BL_ * D_];
__device__ float g_O2[BL_ * D_];
__device__ float g_X[BL_ * D_];
__device__ float g_lat[B_ * 2 * D_];
__device__ float g_psum[(size_t)B_ * H_ * 16 * L_];
__device__ float g_rinv[(size_t)B_ * H_ * L_];

// ---------------------------------------------------------------------------
// helpers
// ---------------------------------------------------------------------------
__device__ __forceinline__ float tf32r(float x) {
    uint32_t o;
    asm("cvt.rna.tf32.f32 %0, %1;" : "=r"(o) : "f"(x));
    return __uint_as_float(o);
}

__device__ __forceinline__ void mma_tf32(float c[4], const float a[4], const float b[2]) {
    asm volatile(
        "mma.sync.aligned.m16n8k8.row.col.f32.tf32.tf32.f32 "
        "{%0,%1,%2,%3}, {%4,%5,%6,%7}, {%8,%9}, {%0,%1,%2,%3};"
        : "+f"(c[0]), "+f"(c[1]), "+f"(c[2]), "+f"(c[3])
        : "r"(__float_as_uint(a[0])), "r"(__float_as_uint(a[1])),
          "r"(__float_as_uint(a[2])), "r"(__float_as_uint(a[3])),
          "r"(__float_as_uint(b[0])), "r"(__float_as_uint(b[1])));
}

__device__ __forceinline__ void cp16(float* dst_smem, const float* src) {
    uint32_t d = (uint32_t)__cvta_generic_to_shared(dst_smem);
    asm volatile("cp.async.cg.shared.global [%0], [%1], 16;" :: "r"(d), "l"(src));
}
#define CP_COMMIT() asm volatile("cp.async.commit_group;")
#define CP_WAIT0()  asm volatile("cp.async.wait_group 0;")
#define CP_WAIT1()  asm volatile("cp.async.wait_group 1;")

// ---------------------------------------------------------------------------
// Double-buffered cp.async TF32 GEMM (dense projections / fc / s2).
// ---------------------------------------------------------------------------
__device__ __forceinline__ void gemm_pipe(
    const float* __restrict__ A, const float* __restrict__ Bg,
    const float* __restrict__ bias, float* __restrict__ C,
    int K, int lda, int ldb, int ldc)
{
    extern __shared__ float sm[];
    float* Asm = sm;                    // [2][BM][36]
    float* Bsm = sm + 2 * ASZ;          // [2][BK][72]

    const int t = threadIdx.x;
    const int lane = t & 31, w = t >> 5;
    const int wm = w & 3, wn = w >> 2;
    const int g = lane >> 2, tg = lane & 3;
    const int row0 = blockIdx.y * BM;
    const int col0 = blockIdx.x * BN;

    float acc[2][4][4] = {};

    {
        #pragma unroll
        for (int i = 0; i < 4; i++) {
            int idx = t + i * NTHR, r = idx >> 3, c4 = (idx & 7) << 2;
            cp16(Asm + r * 36 + c4, A + (size_t)(row0 + r) * lda + c4);
        }
        #pragma unroll
        for (int i = 0; i < 2; i++) {
            int idx = t + i * NTHR, r = idx >> 4, c4 = (idx & 15) << 2;
            cp16(Bsm + r * 72 + c4, Bg + (size_t)r * ldb + col0 + c4);
        }
        CP_COMMIT();
    }

    int buf = 0;
    for (int k0 = 0; k0 < K; k0 += BK) {
        if (k0 + BK < K) {
            float* Ad = Asm + (buf ^ 1) * ASZ;
            float* Bd = Bsm + (buf ^ 1) * BSZ;
            int kn = k0 + BK;
            #pragma unroll
            for (int i = 0; i < 4; i++) {
                int idx = t + i * NTHR, r = idx >> 3, c4 = (idx & 7) << 2;
                cp16(Ad + r * 36 + c4, A + (size_t)(row0 + r) * lda + kn + c4);
            }
            #pragma unroll
            for (int i = 0; i < 2; i++) {
                int idx = t + i * NTHR, r = idx >> 4, c4 = (idx & 15) << 2;
                cp16(Bd + r * 72 + c4, Bg + (size_t)(kn + r) * ldb + col0 + c4);
            }
            CP_COMMIT();
            CP_WAIT1();
        } else {
            CP_WAIT0();
        }
        __syncthreads();

        float* Ab = Asm + buf * ASZ;
        float* Bb = Bsm + buf * BSZ;

        #pragma unroll
        for (int ks = 0; ks < BK; ks += 8) {
            float a[2][4], bf[4][2];
            #pragma unroll
            for (int mt = 0; mt < 2; mt++) {
                int r = wm * 32 + mt * 16 + g;
                a[mt][0] = tf32r(Ab[r * 36 + ks + tg]);
                a[mt][1] = tf32r(Ab[(r + 8) * 36 + ks + tg]);
                a[mt][2] = tf32r(Ab[r * 36 + ks + tg + 4]);
                a[mt][3] = tf32r(Ab[(r + 8) * 36 + ks + tg + 4]);
            }
            #pragma unroll
            for (int nt = 0; nt < 4; nt++) {
                int n = wn * 32 + nt * 8 + g;
                bf[nt][0] = tf32r(Bb[(ks + tg) * 72 + n]);
                bf[nt][1] = tf32r(Bb[(ks + tg + 4) * 72 + n]);
            }
            #pragma unroll
            for (int mt = 0; mt < 2; mt++)
                #pragma unroll
                for (int nt = 0; nt < 4; nt++)
                    mma_tf32(acc[mt][nt], a[mt], bf[nt]);
        }
        __syncthreads();
        buf ^= 1;
    }

    #pragma unroll
    for (int mt = 0; mt < 2; mt++) {
        #pragma unroll
        for (int nt = 0; nt < 4; nt++) {
            int r = row0 + wm * 32 + mt * 16 + g;
            int c = col0 + wn * 32 + nt * 8 + tg * 2;
            float b0 = 0.f, b1 = 0.f;
            if (bias) { b0 = bias[c]; b1 = bias[c + 1]; }
            *(float2*)(C + (size_t)r * ldc + c) =
                make_float2(acc[mt][nt][0] + b0, acc[mt][nt][1] + b1);
            *(float2*)(C + (size_t)(r + 8) * ldc + c) =
                make_float2(acc[mt][nt][2] + b0, acc[mt][nt][3] + b1);
        }
    }
}

// ---------------------------------------------------------------------------
// Pass 1: row sums of exp(QK^T/8). grid (16, 8, 64). No attn write.
// ---------------------------------------------------------------------------
__global__ void __launch_bounds__(256) k_rsum() {
    extern __shared__ float sm[];
    float* Qs = sm;                     // [128][68]
    float* Ks = sm + 128 * 68;          // [64][68]
    float* sPart = Ks + 64 * 68;        // [2][128]

    const int t = threadIdx.x;
    const int lane = t & 31, w = t >> 5;
    const int wm = w & 3, wn = w >> 2;
    const int g = lane >> 2, tg = lane & 3;
    const int z = blockIdx.z, b = z >> 3, h = z & 7;
    const int row0 = blockIdx.y * 128;
    const int col0 = blockIdx.x * 64;

    const float* Qg = g_Q + (size_t)b * L_ * D_ + h * DK_;
    const float* Kg = g_K + (size_t)b * L_ * D_ + h * DK_;

    #pragma unroll
    for (int i = 0; i < 8; i++) {
        int idx = t + i * 256, r = idx >> 4, c4 = (idx & 15) << 2;
        cp16(Qs + r * 68 + c4, Qg + (size_t)(row0 + r) * D_ + c4);
    }
    #pragma unroll
    for (int i = 0; i < 4; i++) {
        int idx = t + i * 256, r = idx >> 4, c4 = (idx & 15) << 2;
        cp16(Ks + r * 68 + c4, Kg + (size_t)(col0 + r) * D_ + c4);
    }
    CP_COMMIT();
    CP_WAIT0();
    __syncthreads();

    float acc[2][4][4] = {};
    #pragma unroll
    for (int ks = 0; ks < DK_; ks += 8) {
        float a[2][4], bf[4][2];
        #pragma unroll
        for (int mt = 0; mt < 2; mt++) {
            int r = wm * 32 + mt * 16 + g;
            a[mt][0] = tf32r(Qs[r * 68 + ks + tg]);
            a[mt][1] = tf32r(Qs[(r + 8) * 68 + ks + tg]);
            a[mt][2] = tf32r(Qs[r * 68 + ks + tg + 4]);
            a[mt][3] = tf32r(Qs[(r + 8) * 68 + ks + tg + 4]);
        }
        #pragma unroll
        for (int nt = 0; nt < 4; nt++) {
            int n = wn * 32 + nt * 8 + g;
            bf[nt][0] = tf32r(Ks[n * 68 + ks + tg]);
            bf[nt][1] = tf32r(Ks[n * 68 + ks + tg + 4]);
        }
        #pragma unroll
        for (int mt = 0; mt < 2; mt++)
            #pragma unroll
            for (int nt = 0; nt < 4; nt++)
                mma_tf32(acc[mt][nt], a[mt], bf[nt]);
    }

    float rs[2][2] = {};
    #pragma unroll
    for (int mt = 0; mt < 2; mt++)
        #pragma unroll
        for (int nt = 0; nt < 4; nt++) {
            rs[mt][0] += __expf(acc[mt][nt][0] * 0.125f) + __expf(acc[mt][nt][1] * 0.125f);
            rs[mt][1] += __expf(acc[mt][nt][2] * 0.125f) + __expf(acc[mt][nt][3] * 0.125f);
        }
    #pragma unroll
    for (int mt = 0; mt < 2; mt++) {
        #pragma unroll
        for (int j = 0; j < 2; j++) {
            rs[mt][j] += __shfl_xor_sync(~0u, rs[mt][j], 1);
            rs[mt][j] += __shfl_xor_sync(~0u, rs[mt][j], 2);
        }
        if (tg == 0) {
            int rl = wm * 32 + mt * 16 + g;
            sPart[wn * 128 + rl] = rs[mt][0];
            sPart[wn * 128 + rl + 8] = rs[mt][1];
        }
    }
    __syncthreads();
    if (t < 128)
        g_psum[((size_t)z * 16 + blockIdx.x) * L_ + row0 + t] =
            sPart[t] + sPart[128 + t];
}

__global__ void k_rowsum() {
    int rid = blockIdx.x * 256 + threadIdx.x;
    int z = rid >> 10, r = rid & 1023;
    float s = 0.f;
    #pragma unroll
    for (int ct = 0; ct < 16; ct++)
        s += g_psum[((size_t)z * 16 + ct) * L_ + r];
    g_rinv[rid] = 1.0f / s;
}

// ---------------------------------------------------------------------------
// Pass 2: recompute S chunkwise, write normalized attn once, accumulate O.
// grid (8 rowblocks, 64 heads), 256 threads, 2 CTAs/SM.
// ---------------------------------------------------------------------------
__global__ void __launch_bounds__(256, 2) k_attn2(float* __restrict__ attn) {
    extern __shared__ float sm[];
    float* Qs = sm + AT_QS;      // [128][68]
    float* Ps = sm + AT_PS;      // [128][68]
    float* Ks = sm + AT_KS;      // [64][68]
    float* Vs = sm + AT_VS;      // [64][72]
    float* sRinv = sm + AT_RI;   // [128]

    const int t = threadIdx.x;
    const int lane = t & 31, w = t >> 5;
    const int wm = w & 3, wn = w >> 2;
    const int g = lane >> 2, tg = lane & 3;
    const int z = blockIdx.y, b = z >> 3, h = z & 7;
    const int row0 = blockIdx.x * 128;

    const float* Qg = g_Q + (size_t)b * L_ * D_ + h * DK_;
    const float* Kg = g_K + (size_t)b * L_ * D_ + h * DK_;
    const float* Vg = g_V + (size_t)b * L_ * D_ + h * DK_;
    float* attn_b = attn + (size_t)z * L_ * L_;

    if (t < 128) sRinv[t] = g_rinv[(size_t)z * L_ + row0 + t];

    #pragma unroll
    for (int i = 0; i < 8; i++) {
        int idx = t + i * 256, r = idx >> 4, c4 = (idx & 15) << 2;
        cp16(Qs + r * 68 + c4, Qg + (size_t)(row0 + r) * D_ + c4);
    }
    CP_COMMIT();

    float accO[2][4][4] = {};

    for (int kc = 0; kc < 16; kc++) {
        __syncthreads();     // previous iter's reads of Ks/Vs/Ps done
        #pragma unroll
        for (int i = 0; i < 4; i++) {
            int idx = t + i * 256, r = idx >> 4, c4 = (idx & 15) << 2;
            cp16(Ks + r * 68 + c4, Kg + (size_t)(kc * 64 + r) * D_ + c4);
        }
        #pragma unroll
        for (int i = 0; i < 4; i++) {
            int idx = t + i * 256, r = idx >> 4, c4 = (idx & 15) << 2;
            cp16(Vs + r * 72 + c4, Vg + (size_t)(kc * 64 + r) * D_ + c4);
        }
        CP_COMMIT();
        CP_WAIT0();
        __syncthreads();

        // ---- S tile (128 x 64) = Q Kt ----
        float acc[2][4][4] = {};
        #pragma unroll
        for (int ks = 0; ks < DK_; ks += 8) {
            float a[2][4], bf[4][2];
            #pragma unroll
            for (int mt = 0; mt < 2; mt++) {
                int r = wm * 32 + mt * 16 + g;
                a[mt][0] = tf32r(Qs[r * 68 + ks + tg]);
                a[mt][1] = tf32r(Qs[(r + 8) * 68 + ks + tg]);
                a[mt][2] = tf32r(Qs[r * 68 + ks + tg + 4]);
                a[mt][3] = tf32r(Qs[(r + 8) * 68 + ks + tg + 4]);
            }
            #pragma unroll
            for (int nt = 0; nt < 4; nt++) {
                int n = wn * 32 + nt * 8 + g;
                bf[nt][0] = tf32r(Ks[n * 68 + ks + tg]);
                bf[nt][1] = tf32r(Ks[n * 68 + ks + tg + 4]);
            }
            #pragma unroll
            for (int mt = 0; mt < 2; mt++)
                #pragma unroll
                for (int nt = 0; nt < 4; nt++)
                    mma_tf32(acc[mt][nt], a[mt], bf[nt]);
        }

        // ---- P = exp(S/8)*rinv -> Ps ----
        #pragma unroll
        for (int mt = 0; mt < 2; mt++) {
            int rl = wm * 32 + mt * 16 + g;
            float r0 = sRinv[rl], r1 = sRinv[rl + 8];
            #pragma unroll
            for (int nt = 0; nt < 4; nt++) {
                int c = wn * 32 + nt * 8 + tg * 2;
                Ps[rl * 68 + c]           = __expf(acc[mt][nt][0] * 0.125f) * r0;
                Ps[rl * 68 + c + 1]       = __expf(acc[mt][nt][1] * 0.125f) * r0;
                Ps[(rl + 8) * 68 + c]     = __expf(acc[mt][nt][2] * 0.125f) * r1;
                Ps[(rl + 8) * 68 + c + 1] = __expf(acc[mt][nt][3] * 0.125f) * r1;
            }
        }
        __syncthreads();

        // ---- write attn chunk (coalesced float4) ----
        #pragma unroll
        for (int i = 0; i < 8; i++) {
            int idx = t + i * 256, r = idx >> 4, c4 = (idx & 15) << 2;
            *(float4*)(attn_b + (size_t)(row0 + r) * L_ + kc * 64 + c4) =
                *(const float4*)(Ps + r * 68 + c4);
        }

        // ---- O += P @ V ----
        #pragma unroll
        for (int ks = 0; ks < 64; ks += 8) {
            float a[2][4], bf[4][2];
            #pragma unroll
            for (int mt = 0; mt < 2; mt++) {
                int r = wm * 32 + mt * 16 + g;
                a[mt][0] = tf32r(Ps[r * 68 + ks + tg]);
                a[mt][1] = tf32r(Ps[(r + 8) * 68 + ks + tg]);
                a[mt][2] = tf32r(Ps[r * 68 + ks + tg + 4]);
                a[mt][3] = tf32r(Ps[(r + 8) * 68 + ks + tg + 4]);
            }
            #pragma unroll
            for (int nt = 0; nt < 4; nt++) {
                int n = wn * 32 + nt * 8 + g;
                bf[nt][0] = tf32r(Vs[(ks + tg) * 72 + n]);
                bf[nt][1] = tf32r(Vs[(ks + tg + 4) * 72 + n]);
            }
            #pragma unroll
            for (int mt = 0; mt < 2; mt++)
                #pragma unroll
                for (int nt = 0; nt < 4; nt++)
                    mma_tf32(accO[mt][nt], a[mt], bf[nt]);
        }
    }

    // ---- epilogue: write O ----
    #pragma unroll
    for (int mt = 0; mt < 2; mt++) {
        #pragma unroll
        for (int nt = 0; nt < 4; nt++) {
            int rl = wm * 32 + mt * 16 + g;
            int c = wn * 32 + nt * 8 + tg * 2;
            float* Og = g_O + (size_t)(b * L_ + row0 + rl) * D_ + h * DK_ + c;
            *(float2*)Og = make_float2(accO[mt][nt][0], accO[mt][nt][1]);
            *(float2*)(Og + 8 * D_) = make_float2(accO[mt][nt][2], accO[mt][nt][3]);
        }
    }
}

// ---------------------------------------------------------------------------
// GEMM wrappers
// ---------------------------------------------------------------------------
__global__ void __launch_bounds__(NTHR) k_proj_qkv(
        const float* __restrict__ q, const float* __restrict__ k,
        const float* __restrict__ v,
        const float* __restrict__ Wq, const float* __restrict__ Wk,
        const float* __restrict__ Wv,
        const float* __restrict__ bq, const float* __restrict__ bk,
        const float* __restrict__ bv) {
    int z = blockIdx.z;
    const float* A = (z == 0) ? q : (z == 1) ? k : v;
    const float* W = (z == 0) ? Wq : (z == 1) ? Wk : Wv;
    const float* bias = (z == 0) ? bq : (z == 1) ? bk : bv;
    float* C = (z == 0) ? g_Q : (z == 1) ? g_K : g_V;
    gemm_pipe(A, W, bias, C, D_, D_, D_, D_);
}

__global__ void __launch_bounds__(NTHR) k_fc(const float* __restrict__ W,
        const float* __restrict__ bias) {
    gemm_pipe(g_O, W, bias, g_O2, D_, D_, D_, D_);
}
__global__ void __launch_bounds__(NTHR) k_s2(const float* __restrict__ W,
        const float* __restrict__ bias) {
    gemm_pipe(g_X, W, bias, g_O, D_, D_, D_, D_);
}

// ---------------------------------------------------------------------------
// small epilogues
// ---------------------------------------------------------------------------
__global__ void k_lat(const float* __restrict__ latent, const float* __restrict__ Ws1,
                      const float* __restrict__ bs1) {
    int b = blockIdx.x;
    __shared__ float sl[D_];
    for (int i = threadIdx.x; i < D_; i += 128) {
        float x = latent[b * D_ + i];
        sl[i] = x / (1.0f + __expf(-x));
    }
    __syncthreads();
    int j = blockIdx.y * 128 + threadIdx.x;
    float acc = bs1[j];
    for (int k = 0; k < D_; k++) acc += sl[k] * Ws1[(size_t)k * (2 * D_) + j];
    g_lat[b * (2 * D_) + j] = acc;
}

__global__ void k_film(const float* __restrict__ en_g, const float* __restrict__ en_b) {
    int row = blockIdx.x;
    int b = row >> 10;
    int t = threadIdx.x;
    float4 v = ((const float4*)(g_O2 + (size_t)row * D_))[t];
    __shared__ float red[128];

    red[t] = v.x + v.y + v.z + v.w;
    __syncthreads();
    for (int s = 64; s > 0; s >>= 1) {
        if (t < s) red[t] += red[t + s];
        __syncthreads();
    }
    float mean = red[0] * (1.0f / D_);
    __syncthreads();

    float dx = v.x - mean, dy = v.y - mean, dz = v.z - mean, dw = v.w - mean;
    red[t] = dx * dx + dy * dy + dz * dz + dw * dw;
    __syncthreads();
    for (int s = 64; s > 0; s >>= 1) {
        if (t < s) red[t] += red[t + s];
        __syncthreads();
    }
    float rstd = rsqrtf(red[0] * (1.0f / D_) + 1e-5f);

    int j = t * 4;
    float4 g4 = ((const float4*)en_g)[t];
    float4 b4 = ((const float4*)en_b)[t];
    float4 sc = *(const float4*)(g_lat + b * (2 * D_) + j);
    float4 sh = *(const float4*)(g_lat + b * (2 * D_) + D_ + j);

    float4 o;
    {
        float h;
        h = (dx * rstd * g4.x + b4.x) * (1.0f + sc.x) + sh.x; o.x = h / (1.0f + __expf(-h));
        h = (dy * rstd * g4.y + b4.y) * (1.0f + sc.y) + sh.y; o.y = h / (1.0f + __expf(-h));
        h = (dz * rstd * g4.z + b4.z) * (1.0f + sc.z) + sh.z; o.z = h / (1.0f + __expf(-h));
        h = (dw * rstd * g4.w + b4.w) * (1.0f + sc.w) + sh.w; o.w = h / (1.0f + __expf(-h));
    }
    ((float4*)(g_X + (size_t)row * D_))[t] = o;
}

__global__ void k_final(const float* __restrict__ resid, const float* __restrict__ ln_g,
                        const float* __restrict__ ln_b, float* __restrict__ out) {
    int row = blockIdx.x;
    int t = threadIdx.x;
    float4 v = ((const float4*)(g_O + (size_t)row * D_))[t];
    float4 r = ((const float4*)(resid + (size_t)row * D_))[t];
    v.x += r.x; v.y += r.y; v.z += r.z; v.w += r.w;
    __shared__ float red[128];

    red[t] = v.x + v.y + v.z + v.w;
    __syncthreads();
    for (int s = 64; s > 0; s >>= 1) {
        if (t < s) red[t] += red[t + s];
        __syncthreads();
    }
    float mean = red[0] * (1.0f / D_);
    __syncthreads();

    float dx = v.x - mean, dy = v.y - mean, dz = v.z - mean, dw = v.w - mean;
    red[t] = dx * dx + dy * dy + dz * dz + dw * dw;
    __syncthreads();
    for (int s = 64; s > 0; s >>= 1) {
        if (t < s) red[t] += red[t + s];
        __syncthreads();
    }
    float rstd = rsqrtf(red[0] * (1.0f / D_) + 1e-6f);

    float4 g4 = ((const float4*)ln_g)[t];
    float4 b4 = ((const float4*)ln_b)[t];
    float4 o;
    o.x = dx * rstd * g4.x + b4.x;
    o.y = dy * rstd * g4.y + b4.y;
    o.z = dz * rstd * g4.z + b4.z;
    o.w = dw * rstd * g4.w + b4.w;
    ((float4*)(out + (size_t)row * D_))[t] = o;
}

// ---------------------------------------------------------------------------
extern "C" void kernel_launch(void* const* d_in, const int* in_sizes, int n_in,
                              void* d_out, int out_size) {
    const float* q      = (const float*)d_in[0];
    const float* k      = (const float*)d_in[1];
    const float* v      = (const float*)d_in[2];
    const float* latent = (const float*)d_in[3];
    const float* Wq  = (const float*)d_in[4];
    const float* bq  = (const float*)d_in[5];
    const float* Wk  = (const float*)d_in[6];
    const float* bk  = (const float*)d_in[7];
    const float* Wv  = (const float*)d_in[8];
    const float* bv  = (const float*)d_in[9];
    const float* Wfc = (const float*)d_in[10];
    const float* bfc = (const float*)d_in[11];
    const float* Ws1 = (const float*)d_in[12];
    const float* bs1 = (const float*)d_in[13];
    const float* Ws2 = (const float*)d_in[14];
    const float* bs2 = (const float*)d_in[15];
    const float* en_g = (const float*)d_in[16];
    const float* en_b = (const float*)d_in[17];
    const float* ln_g = (const float*)d_in[18];
    const float* ln_b = (const float*)d_in[19];

    float* out  = (float*)d_out;
    float* attn = out + ATT_OFF;

    cudaFuncSetAttribute(k_proj_qkv, cudaFuncAttributeMaxDynamicSharedMemorySize, SMEM_GEMM);
    cudaFuncSetAttribute(k_fc,   cudaFuncAttributeMaxDynamicSharedMemorySize, SMEM_GEMM);
    cudaFuncSetAttribute(k_s2,   cudaFuncAttributeMaxDynamicSharedMemorySize, SMEM_GEMM);
    cudaFuncSetAttribute(k_rsum, cudaFuncAttributeMaxDynamicSharedMemorySize, SMEM_SC);
    cudaFuncSetAttribute(k_attn2, cudaFuncAttributeMaxDynamicSharedMemorySize, AT_SMEM);

    dim3 t256(NTHR);
    dim3 gProj(D_ / BN, BL_ / BM);          // (8, 64)

    k_proj_qkv<<<dim3(D_ / BN, BL_ / BM, 3), t256, SMEM_GEMM>>>(
        q, k, v, Wq, Wk, Wv, bq, bk, bv);

    k_rsum<<<dim3(L_ / 64, L_ / 128, B_ * H_), t256, SMEM_SC>>>();
    k_rowsum<<<(B_ * H_ * L_) / 256, 256>>>();
    k_attn2<<<dim3(L_ / 128, B_ * H_), t256, AT_SMEM>>>(attn);

    k_fc<<<gProj, t256, SMEM_GEMM>>>(Wfc, bfc);
    k_lat<<<dim3(B_, 8), 128>>>(latent, Ws1, bs1);
    k_film<<<BL_, 128>>>(en_g, en_b);
    k_s2<<<gProj, t256, SMEM_GEMM>>>(Ws2, bs2);
    k_final<<<BL_, 128>>>(q, ln_g, ln_b, out);
}

// round 8
// speedup vs baseline: 1.0049x; 1.0049x over previous
#include <cuda_runtime.h>
#include <cstdint>

// Problem dims
#define B_ 8
#define L_ 1024
#define D_ 512
#define H_ 8
#define DK_ 64
#define BL_ (B_ * L_)               // 8192
#define ATT_OFF ((size_t)BL_ * D_)  // start of attn in d_out

// GEMM tile config
#define BM 128
#define BN 64
#define BK 32
#define NTHR 256

#define ASZ (BM * 36)       // A stage floats
#define BSZ (BK * 72)       // B stage floats
#define SMEM_GEMM ((2 * ASZ + 2 * BSZ + 128) * 4)        // 55808 B
#define SMEM_SC   ((128 * 68 + 64 * 68 + 256) * 4)       // pass-1

// k_attn2 smem (QB=64): Qs[64][68] Ps[64][68] Ks[64][68] Vs[64][72] rinv[64]
#define A2_QS 0
#define A2_PS (64 * 68)
#define A2_KS (A2_PS + 64 * 68)
#define A2_VS (A2_KS + 64 * 68)
#define A2_RI (A2_VS + 64 * 72)
#define A2_SMEM ((A2_RI + 64) * 4)      // 70,912 B -> 3 CTAs/SM

// Scratch (static device globals — no allocation)
__device__ float g_Q[BL_ * D_];
__device__ float g_K[BL_ * D_];
__device__ float g_V[BL_ * D_];
__device__ float g_O[BL_ * D_];
__device__ float g_O2[BL_ * D_];
__device__ float g_X[BL_ * D_];
__device__ float g_lat[B_ * 2 * D_];
__device__ float g_psum[(size_t)B_ * H_ * 16 * L_];
__device__ float g_rinv[(size_t)B_ * H_ * L_];

// ---------------------------------------------------------------------------
// helpers
// ---------------------------------------------------------------------------
__device__ __forceinline__ float tf32r(float x) {
    uint32_t o;
    asm("cvt.rna.tf32.f32 %0, %1;" : "=r"(o) : "f"(x));
    return __uint_as_float(o);
}

__device__ __forceinline__ void mma_tf32(float c[4], const float a[4], const float b[2]) {
    asm volatile(
        "mma.sync.aligned.m16n8k8.row.col.f32.tf32.tf32.f32 "
        "{%0,%1,%2,%3}, {%4,%5,%6,%7}, {%8,%9}, {%0,%1,%2,%3};"
        : "+f"(c[0]), "+f"(c[1]), "+f"(c[2]), "+f"(c[3])
        : "r"(__float_as_uint(a[0])), "r"(__float_as_uint(a[1])),
          "r"(__float_as_uint(a[2])), "r"(__float_as_uint(a[3])),
          "r"(__float_as_uint(b[0])), "r"(__float_as_uint(b[1])));
}

__device__ __forceinline__ void cp16(float* dst_smem, const float* src) {
    uint32_t d = (uint32_t)__cvta_generic_to_shared(dst_smem);
    asm volatile("cp.async.cg.shared.global [%0], [%1], 16;" :: "r"(d), "l"(src));
}
#define CP_COMMIT() asm volatile("cp.async.commit_group;")
#define CP_WAIT0()  asm volatile("cp.async.wait_group 0;")
#define CP_WAIT1()  asm volatile("cp.async.wait_group 1;")

// ---------------------------------------------------------------------------
// Double-buffered cp.async TF32 GEMM. RND: round C to tf32 on store
// (used for Q/K/V so downstream kernels skip per-fragment cvt).
// ---------------------------------------------------------------------------
template <bool RND>
__device__ __forceinline__ void gemm_pipe(
    const float* __restrict__ A, const float* __restrict__ Bg,
    const float* __restrict__ bias, float* __restrict__ C,
    int K, int lda, int ldb, int ldc)
{
    extern __shared__ float sm[];
    float* Asm = sm;                    // [2][BM][36]
    float* Bsm = sm + 2 * ASZ;          // [2][BK][72]

    const int t = threadIdx.x;
    const int lane = t & 31, w = t >> 5;
    const int wm = w & 3, wn = w >> 2;
    const int g = lane >> 2, tg = lane & 3;
    const int row0 = blockIdx.y * BM;
    const int col0 = blockIdx.x * BN;

    float acc[2][4][4] = {};

    {
        #pragma unroll
        for (int i = 0; i < 4; i++) {
            int idx = t + i * NTHR, r = idx >> 3, c4 = (idx & 7) << 2;
            cp16(Asm + r * 36 + c4, A + (size_t)(row0 + r) * lda + c4);
        }
        #pragma unroll
        for (int i = 0; i < 2; i++) {
            int idx = t + i * NTHR, r = idx >> 4, c4 = (idx & 15) << 2;
            cp16(Bsm + r * 72 + c4, Bg + (size_t)r * ldb + col0 + c4);
        }
        CP_COMMIT();
    }

    int buf = 0;
    for (int k0 = 0; k0 < K; k0 += BK) {
        if (k0 + BK < K) {
            float* Ad = Asm + (buf ^ 1) * ASZ;
            float* Bd = Bsm + (buf ^ 1) * BSZ;
            int kn = k0 + BK;
            #pragma unroll
            for (int i = 0; i < 4; i++) {
                int idx = t + i * NTHR, r = idx >> 3, c4 = (idx & 7) << 2;
                cp16(Ad + r * 36 + c4, A + (size_t)(row0 + r) * lda + kn + c4);
            }
            #pragma unroll
            for (int i = 0; i < 2; i++) {
                int idx = t + i * NTHR, r = idx >> 4, c4 = (idx & 15) << 2;
                cp16(Bd + r * 72 + c4, Bg + (size_t)(kn + r) * ldb + col0 + c4);
            }
            CP_COMMIT();
            CP_WAIT1();
        } else {
            CP_WAIT0();
        }
        __syncthreads();

        float* Ab = Asm + buf * ASZ;
        float* Bb = Bsm + buf * BSZ;

        #pragma unroll
        for (int ks = 0; ks < BK; ks += 8) {
            float a[2][4], bf[4][2];
            #pragma unroll
            for (int mt = 0; mt < 2; mt++) {
                int r = wm * 32 + mt * 16 + g;
                a[mt][0] = tf32r(Ab[r * 36 + ks + tg]);
                a[mt][1] = tf32r(Ab[(r + 8) * 36 + ks + tg]);
                a[mt][2] = tf32r(Ab[r * 36 + ks + tg + 4]);
                a[mt][3] = tf32r(Ab[(r + 8) * 36 + ks + tg + 4]);
            }
            #pragma unroll
            for (int nt = 0; nt < 4; nt++) {
                int n = wn * 32 + nt * 8 + g;
                bf[nt][0] = tf32r(Bb[(ks + tg) * 72 + n]);
                bf[nt][1] = tf32r(Bb[(ks + tg + 4) * 72 + n]);
            }
            #pragma unroll
            for (int mt = 0; mt < 2; mt++)
                #pragma unroll
                for (int nt = 0; nt < 4; nt++)
                    mma_tf32(acc[mt][nt], a[mt], bf[nt]);
        }
        __syncthreads();
        buf ^= 1;
    }

    #pragma unroll
    for (int mt = 0; mt < 2; mt++) {
        #pragma unroll
        for (int nt = 0; nt < 4; nt++) {
            int r = row0 + wm * 32 + mt * 16 + g;
            int c = col0 + wn * 32 + nt * 8 + tg * 2;
            float b0 = 0.f, b1 = 0.f;
            if (bias) { b0 = bias[c]; b1 = bias[c + 1]; }
            float o0 = acc[mt][nt][0] + b0, o1 = acc[mt][nt][1] + b1;
            float o2 = acc[mt][nt][2] + b0, o3 = acc[mt][nt][3] + b1;
            if (RND) { o0 = tf32r(o0); o1 = tf32r(o1); o2 = tf32r(o2); o3 = tf32r(o3); }
            *(float2*)(C + (size_t)r * ldc + c) = make_float2(o0, o1);
            *(float2*)(C + (size_t)(r + 8) * ldc + c) = make_float2(o2, o3);
        }
    }
}

// ---------------------------------------------------------------------------
// Pass 1: row sums of exp(QK^T/8). grid (16, 8, 64). Q/K pre-rounded.
// ---------------------------------------------------------------------------
__global__ void __launch_bounds__(256) k_rsum() {
    extern __shared__ float sm[];
    float* Qs = sm;                     // [128][68]
    float* Ks = sm + 128 * 68;          // [64][68]
    float* sPart = Ks + 64 * 68;        // [2][128]

    const int t = threadIdx.x;
    const int lane = t & 31, w = t >> 5;
    const int wm = w & 3, wn = w >> 2;
    const int g = lane >> 2, tg = lane & 3;
    const int z = blockIdx.z, b = z >> 3, h = z & 7;
    const int row0 = blockIdx.y * 128;
    const int col0 = blockIdx.x * 64;

    const float* Qg = g_Q + (size_t)b * L_ * D_ + h * DK_;
    const float* Kg = g_K + (size_t)b * L_ * D_ + h * DK_;

    #pragma unroll
    for (int i = 0; i < 8; i++) {
        int idx = t + i * 256, r = idx >> 4, c4 = (idx & 15) << 2;
        cp16(Qs + r * 68 + c4, Qg + (size_t)(row0 + r) * D_ + c4);
    }
    #pragma unroll
    for (int i = 0; i < 4; i++) {
        int idx = t + i * 256, r = idx >> 4, c4 = (idx & 15) << 2;
        cp16(Ks + r * 68 + c4, Kg + (size_t)(col0 + r) * D_ + c4);
    }
    CP_COMMIT();
    CP_WAIT0();
    __syncthreads();

    float acc[2][4][4] = {};
    #pragma unroll
    for (int ks = 0; ks < DK_; ks += 8) {
        float a[2][4], bf[4][2];
        #pragma unroll
        for (int mt = 0; mt < 2; mt++) {
            int r = wm * 32 + mt * 16 + g;
            a[mt][0] = Qs[r * 68 + ks + tg];
            a[mt][1] = Qs[(r + 8) * 68 + ks + tg];
            a[mt][2] = Qs[r * 68 + ks + tg + 4];
            a[mt][3] = Qs[(r + 8) * 68 + ks + tg + 4];
        }
        #pragma unroll
        for (int nt = 0; nt < 4; nt++) {
            int n = wn * 32 + nt * 8 + g;
            bf[nt][0] = Ks[n * 68 + ks + tg];
            bf[nt][1] = Ks[n * 68 + ks + tg + 4];
        }
        #pragma unroll
        for (int mt = 0; mt < 2; mt++)
            #pragma unroll
            for (int nt = 0; nt < 4; nt++)
                mma_tf32(acc[mt][nt], a[mt], bf[nt]);
    }

    float rs[2][2] = {};
    #pragma unroll
    for (int mt = 0; mt < 2; mt++)
        #pragma unroll
        for (int nt = 0; nt < 4; nt++) {
            rs[mt][0] += __expf(acc[mt][nt][0] * 0.125f) + __expf(acc[mt][nt][1] * 0.125f);
            rs[mt][1] += __expf(acc[mt][nt][2] * 0.125f) + __expf(acc[mt][nt][3] * 0.125f);
        }
    #pragma unroll
    for (int mt = 0; mt < 2; mt++) {
        #pragma unroll
        for (int j = 0; j < 2; j++) {
            rs[mt][j] += __shfl_xor_sync(~0u, rs[mt][j], 1);
            rs[mt][j] += __shfl_xor_sync(~0u, rs[mt][j], 2);
        }
        if (tg == 0) {
            int rl = wm * 32 + mt * 16 + g;
            sPart[wn * 128 + rl] = rs[mt][0];
            sPart[wn * 128 + rl + 8] = rs[mt][1];
        }
    }
    __syncthreads();
    if (t < 128)
        g_psum[((size_t)z * 16 + blockIdx.x) * L_ + row0 + t] =
            sPart[t] + sPart[128 + t];
}

__global__ void k_rowsum() {
    int rid = blockIdx.x * 256 + threadIdx.x;
    int z = rid >> 10, r = rid & 1023;
    float s = 0.f;
    #pragma unroll
    for (int ct = 0; ct < 16; ct++)
        s += g_psum[((size_t)z * 16 + ct) * L_ + r];
    g_rinv[rid] = 1.0f / s;
}

// ---------------------------------------------------------------------------
// Pass 2: recompute S chunkwise, write normalized attn once, accumulate O.
// QB=64 rows/CTA: grid (16, 64), 256 threads, 3 CTAs/SM.
// Warp grid 2(m) x 4(n): each warp 32 rows x 16 cols.
// ---------------------------------------------------------------------------
__global__ void __launch_bounds__(256, 3) k_attn2(float* __restrict__ attn) {
    extern __shared__ float sm[];
    float* Qs = sm + A2_QS;      // [64][68]
    float* Ps = sm + A2_PS;      // [64][68]
    float* Ks = sm + A2_KS;      // [64][68]
    float* Vs = sm + A2_VS;      // [64][72]
    float* sRinv = sm + A2_RI;   // [64]

    const int t = threadIdx.x;
    const int lane = t & 31, w = t >> 5;
    const int wm = w & 1, wn = w >> 1;
    const int g = lane >> 2, tg = lane & 3;
    const int z = blockIdx.y, b = z >> 3, h = z & 7;
    const int row0 = blockIdx.x * 64;

    const float* Qg = g_Q + (size_t)b * L_ * D_ + h * DK_;
    const float* Kg = g_K + (size_t)b * L_ * D_ + h * DK_;
    const float* Vg = g_V + (size_t)b * L_ * D_ + h * DK_;
    float* attn_b = attn + (size_t)z * L_ * L_;

    if (t < 64) sRinv[t] = g_rinv[(size_t)z * L_ + row0 + t];

    #pragma unroll
    for (int i = 0; i < 4; i++) {
        int idx = t + i * 256, r = idx >> 4, c4 = (idx & 15) << 2;
        cp16(Qs + r * 68 + c4, Qg + (size_t)(row0 + r) * D_ + c4);
    }
    CP_COMMIT();

    float accO[2][2][4] = {};

    for (int kc = 0; kc < 16; kc++) {
        __syncthreads();     // prior reads of Ks/Vs/Ps done
        #pragma unroll
        for (int i = 0; i < 4; i++) {
            int idx = t + i * 256, r = idx >> 4, c4 = (idx & 15) << 2;
            cp16(Ks + r * 68 + c4, Kg + (size_t)(kc * 64 + r) * D_ + c4);
        }
        #pragma unroll
        for (int i = 0; i < 4; i++) {
            int idx = t + i * 256, r = idx >> 4, c4 = (idx & 15) << 2;
            cp16(Vs + r * 72 + c4, Vg + (size_t)(kc * 64 + r) * D_ + c4);
        }
        CP_COMMIT();
        CP_WAIT0();
        __syncthreads();

        // ---- S tile (64 x 64) = Q Kt ----
        float acc[2][2][4] = {};
        #pragma unroll
        for (int ks = 0; ks < DK_; ks += 8) {
            float a[2][4], bf[2][2];
            #pragma unroll
            for (int mt = 0; mt < 2; mt++) {
                int r = wm * 32 + mt * 16 + g;
                a[mt][0] = Qs[r * 68 + ks + tg];
                a[mt][1] = Qs[(r + 8) * 68 + ks + tg];
                a[mt][2] = Qs[r * 68 + ks + tg + 4];
                a[mt][3] = Qs[(r + 8) * 68 + ks + tg + 4];
            }
            #pragma unroll
            for (int nt = 0; nt < 2; nt++) {
                int n = wn * 16 + nt * 8 + g;
                bf[nt][0] = Ks[n * 68 + ks + tg];
                bf[nt][1] = Ks[n * 68 + ks + tg + 4];
            }
            #pragma unroll
            for (int mt = 0; mt < 2; mt++)
                #pragma unroll
                for (int nt = 0; nt < 2; nt++)
                    mma_tf32(acc[mt][nt], a[mt], bf[nt]);
        }

        // ---- P = exp(S/8)*rinv -> Ps ----
        #pragma unroll
        for (int mt = 0; mt < 2; mt++) {
            int rl = wm * 32 + mt * 16 + g;
            float r0 = sRinv[rl], r1 = sRinv[rl + 8];
            #pragma unroll
            for (int nt = 0; nt < 2; nt++) {
                int c = wn * 16 + nt * 8 + tg * 2;
                Ps[rl * 68 + c]           = __expf(acc[mt][nt][0] * 0.125f) * r0;
                Ps[rl * 68 + c + 1]       = __expf(acc[mt][nt][1] * 0.125f) * r0;
                Ps[(rl + 8) * 68 + c]     = __expf(acc[mt][nt][2] * 0.125f) * r1;
                Ps[(rl + 8) * 68 + c + 1] = __expf(acc[mt][nt][3] * 0.125f) * r1;
            }
        }
        __syncthreads();

        // ---- write attn chunk (coalesced float4) ----
        #pragma unroll
        for (int i = 0; i < 4; i++) {
            int idx = t + i * 256, r = idx >> 4, c4 = (idx & 15) << 2;
            *(float4*)(attn_b + (size_t)(row0 + r) * L_ + kc * 64 + c4) =
                *(const float4*)(Ps + r * 68 + c4);
        }

        // ---- O += P @ V ----
        #pragma unroll
        for (int ks = 0; ks < 64; ks += 8) {
            float a[2][4], bf[2][2];
            #pragma unroll
            for (int mt = 0; mt < 2; mt++) {
                int r = wm * 32 + mt * 16 + g;
                a[mt][0] = tf32r(Ps[r * 68 + ks + tg]);
                a[mt][1] = tf32r(Ps[(r + 8) * 68 + ks + tg]);
                a[mt][2] = tf32r(Ps[r * 68 + ks + tg + 4]);
                a[mt][3] = tf32r(Ps[(r + 8) * 68 + ks + tg + 4]);
            }
            #pragma unroll
            for (int nt = 0; nt < 2; nt++) {
                int n = wn * 16 + nt * 8 + g;
                bf[nt][0] = Vs[(ks + tg) * 72 + n];
                bf[nt][1] = Vs[(ks + tg + 4) * 72 + n];
            }
            #pragma unroll
            for (int mt = 0; mt < 2; mt++)
                #pragma unroll
                for (int nt = 0; nt < 2; nt++)
                    mma_tf32(accO[mt][nt], a[mt], bf[nt]);
        }
    }

    // ---- epilogue: write O ----
    #pragma unroll
    for (int mt = 0; mt < 2; mt++) {
        #pragma unroll
        for (int nt = 0; nt < 2; nt++) {
            int rl = wm * 32 + mt * 16 + g;
            int c = wn * 16 + nt * 8 + tg * 2;
            float* Og = g_O + (size_t)(b * L_ + row0 + rl) * D_ + h * DK_ + c;
            *(float2*)Og = make_float2(accO[mt][nt][0], accO[mt][nt][1]);
            *(float2*)(Og + 8 * D_) = make_float2(accO[mt][nt][2], accO[mt][nt][3]);
        }
    }
}

// ---------------------------------------------------------------------------
// GEMM wrappers
// ---------------------------------------------------------------------------
__global__ void __launch_bounds__(NTHR) k_proj_qkv(
        const float* __restrict__ q, const float* __restrict__ k,
        const float* __restrict__ v,
        const float* __restrict__ Wq, const float* __restrict__ Wk,
        const float* __restrict__ Wv,
        const float* __restrict__ bq, const float* __restrict__ bk,
        const float* __restrict__ bv) {
    int z = blockIdx.z;
    const float* A = (z == 0) ? q : (z == 1) ? k : v;
    const float* W = (z == 0) ? Wq : (z == 1) ? Wk : Wv;
    const float* bias = (z == 0) ? bq : (z == 1) ? bk : bv;
    float* C = (z == 0) ? g_Q : (z == 1) ? g_K : g_V;
    gemm_pipe<true>(A, W, bias, C, D_, D_, D_, D_);
}

__global__ void __launch_bounds__(NTHR) k_fc(const float* __restrict__ W,
        const float* __restrict__ bias) {
    gemm_pipe<false>(g_O, W, bias, g_O2, D_, D_, D_, D_);
}
__global__ void __launch_bounds__(NTHR) k_s2(const float* __restrict__ W,
        const float* __restrict__ bias) {
    gemm_pipe<false>(g_X, W, bias, g_O, D_, D_, D_, D_);
}

// ---------------------------------------------------------------------------
// small epilogues
// ---------------------------------------------------------------------------
__global__ void k_lat(const float* __restrict__ latent, const float* __restrict__ Ws1,
                      const float* __restrict__ bs1) {
    int b = blockIdx.x;
    __shared__ float sl[D_];
    for (int i = threadIdx.x; i < D_; i += 128) {
        float x = latent[b * D_ + i];
        sl[i] = x / (1.0f + __expf(-x));
    }
    __syncthreads();
    int j = blockIdx.y * 128 + threadIdx.x;
    float acc = bs1[j];
    for (int k = 0; k < D_; k++) acc += sl[k] * Ws1[(size_t)k * (2 * D_) + j];
    g_lat[b * (2 * D_) + j] = acc;
}

__global__ void k_film(const float* __restrict__ en_g, const float* __restrict__ en_b) {
    int row = blockIdx.x;
    int b = row >> 10;
    int t = threadIdx.x;
    float4 v = ((const float4*)(g_O2 + (size_t)row * D_))[t];
    __shared__ float red[128];

    red[t] = v.x + v.y + v.z + v.w;
    __syncthreads();
    for (int s = 64; s > 0; s >>= 1) {
        if (t < s) red[t] += red[t + s];
        __syncthreads();
    }
    float mean = red[0] * (1.0f / D_);
    __syncthreads();

    float dx = v.x - mean, dy = v.y - mean, dz = v.z - mean, dw = v.w - mean;
    red[t] = dx * dx + dy * dy + dz * dz + dw * dw;
    __syncthreads();
    for (int s = 64; s > 0; s >>= 1) {
        if (t < s) red[t] += red[t + s];
        __syncthreads();
    }
    float rstd = rsqrtf(red[0] * (1.0f / D_) + 1e-5f);

    int j = t * 4;
    float4 g4 = ((const float4*)en_g)[t];
    float4 b4 = ((const float4*)en_b)[t];
    float4 sc = *(const float4*)(g_lat + b * (2 * D_) + j);
    float4 sh = *(const float4*)(g_lat + b * (2 * D_) + D_ + j);

    float4 o;
    {
        float h;
        h = (dx * rstd * g4.x + b4.x) * (1.0f + sc.x) + sh.x; o.x = h / (1.0f + __expf(-h));
        h = (dy * rstd * g4.y + b4.y) * (1.0f + sc.y) + sh.y; o.y = h / (1.0f + __expf(-h));
        h = (dz * rstd * g4.z + b4.z) * (1.0f + sc.z) + sh.z; o.z = h / (1.0f + __expf(-h));
        h = (dw * rstd * g4.w + b4.w) * (1.0f + sc.w) + sh.w; o.w = h / (1.0f + __expf(-h));
    }
    ((float4*)(g_X + (size_t)row * D_))[t] = o;
}

__global__ void k_final(const float* __restrict__ resid, const float* __restrict__ ln_g,
                        const float* __restrict__ ln_b, float* __restrict__ out) {
    int row = blockIdx.x;
    int t = threadIdx.x;
    float4 v = ((const float4*)(g_O + (size_t)row * D_))[t];
    float4 r = ((const float4*)(resid + (size_t)row * D_))[t];
    v.x += r.x; v.y += r.y; v.z += r.z; v.w += r.w;
    __shared__ float red[128];

    red[t] = v.x + v.y + v.z + v.w;
    __syncthreads();
    for (int s = 64; s > 0; s >>= 1) {
        if (t < s) red[t] += red[t + s];
        __syncthreads();
    }
    float mean = red[0] * (1.0f / D_);
    __syncthreads();

    float dx = v.x - mean, dy = v.y - mean, dz = v.z - mean, dw = v.w - mean;
    red[t] = dx * dx + dy * dy + dz * dz + dw * dw;
    __syncthreads();
    for (int s = 64; s > 0; s >>= 1) {
        if (t < s) red[t] += red[t + s];
        __syncthreads();
    }
    float rstd = rsqrtf(red[0] * (1.0f / D_) + 1e-6f);

    float4 g4 = ((const float4*)ln_g)[t];
    float4 b4 = ((const float4*)ln_b)[t];
    float4 o;
    o.x = dx * rstd * g4.x + b4.x;
    o.y = dy * rstd * g4.y + b4.y;
    o.z = dz * rstd * g4.z + b4.z;
    o.w = dw * rstd * g4.w + b4.w;
    ((float4*)(out + (size_t)row * D_))[t] = o;
}

// ---------------------------------------------------------------------------
extern "C" void kernel_launch(void* const* d_in, const int* in_sizes, int n_in,
                              void* d_out, int out_size) {
    const float* q      = (const float*)d_in[0];
    const float* k      = (const float*)d_in[1];
    const float* v      = (const float*)d_in[2];
    const float* latent = (const float*)d_in[3];
    const float* Wq  = (const float*)d_in[4];
    const float* bq  = (const float*)d_in[5];
    const float* Wk  = (const float*)d_in[6];
    const float* bk  = (const float*)d_in[7];
    const float* Wv  = (const float*)d_in[8];
    const float* bv  = (const float*)d_in[9];
    const float* Wfc = (const float*)d_in[10];
    const float* bfc = (const float*)d_in[11];
    const float* Ws1 = (const float*)d_in[12];
    const float* bs1 = (const float*)d_in[13];
    const float* Ws2 = (const float*)d_in[14];
    const float* bs2 = (const float*)d_in[15];
    const float* en_g = (const float*)d_in[16];
    const float* en_b = (const float*)d_in[17];
    const float* ln_g = (const float*)d_in[18];
    const float* ln_b = (const float*)d_in[19];

    float* out  = (float*)d_out;
    float* attn = out + ATT_OFF;

    cudaFuncSetAttribute(k_proj_qkv, cudaFuncAttributeMaxDynamicSharedMemorySize, SMEM_GEMM);
    cudaFuncSetAttribute(k_fc,   cudaFuncAttributeMaxDynamicSharedMemorySize, SMEM_GEMM);
    cudaFuncSetAttribute(k_s2,   cudaFuncAttributeMaxDynamicSharedMemorySize, SMEM_GEMM);
    cudaFuncSetAttribute(k_rsum, cudaFuncAttributeMaxDynamicSharedMemorySize, SMEM_SC);
    cudaFuncSetAttribute(k_attn2, cudaFuncAttributeMaxDynamicSharedMemorySize, A2_SMEM);

    dim3 t256(NTHR);
    dim3 gProj(D_ / BN, BL_ / BM);          // (8, 64)

    k_proj_qkv<<<dim3(D_ / BN, BL_ / BM, 3), t256, SMEM_GEMM>>>(
        q, k, v, Wq, Wk, Wv, bq, bk, bv);

    k_rsum<<<dim3(L_ / 64, L_ / 128, B_ * H_), t256, SMEM_SC>>>();
    k_rowsum<<<(B_ * H_ * L_) / 256, 256>>>();
    k_attn2<<<dim3(L_ / 64, B_ * H_), t256, A2_SMEM>>>(attn);

    k_fc<<<gProj, t256, SMEM_GEMM>>>(Wfc, bfc);
    k_lat<<<dim3(B_, 8), 128>>>(latent, Ws1, bs1);
    k_film<<<BL_, 128>>>(en_g, en_b);
    k_s2<<<gProj, t256, SMEM_GEMM>>>(Ws2, bs2);
    k_final<<<BL_, 128>>>(q, ln_g, ln_b, out);
}